// round 5
// baseline (speedup 1.0000x reference)
#include <cuda_runtime.h>
#include <math.h>

#define NB   2
#define NS   4096
#define NE   2560
#define NH   8
#define NKV  4
#define ND   256
#define NWIN 1024

// ---------------- scratch (device globals: allocation-free) ----------------
static __device__ float g_qkv[(size_t)NB * NS * (NH + 2 * NKV) * ND]; // [8192, 4096]
static __device__ float g_q  [(size_t)NB * NH  * NS * ND];            // [b,h,s,d]
static __device__ float g_k  [(size_t)NB * NKV * NS * ND];            // [b,kh,s,d]
static __device__ float g_v  [(size_t)NB * NKV * NS * ND];
static __device__ float g_att[(size_t)NB * NS * NH * ND];             // [b,s,h*d]

__device__ __forceinline__ unsigned f2tf32(float f) {
    unsigned u;
    asm volatile("cvt.rna.tf32.f32 %0, %1;" : "=r"(u) : "f"(f));
    return u;
}

__device__ __forceinline__ void mma_tf32(float* d,
        unsigned a0, unsigned a1, unsigned a2, unsigned a3,
        unsigned b0, unsigned b1) {
    asm volatile(
        "mma.sync.aligned.m16n8k8.row.col.f32.tf32.tf32.f32 "
        "{%0,%1,%2,%3},{%4,%5,%6,%7},{%8,%9},{%0,%1,%2,%3};"
        : "+f"(d[0]), "+f"(d[1]), "+f"(d[2]), "+f"(d[3])
        : "r"(a0), "r"(a1), "r"(a2), "r"(a3), "r"(b0), "r"(b1));
}

// ---------------------------------------------------------------------------
// TF32 tensor-core GEMM: C[M,N] = A[M,K] @ B[N,K]^T  (row-major, K contiguous)
// 128x128 block tile, BK=32, 512 threads (16 warps, 4x4 grid, 32x32 each).
// ---------------------------------------------------------------------------
#define SPITCH 36

__global__ __launch_bounds__(512, 1) void tf32gemm_nt(
        const float* __restrict__ A, const float* __restrict__ Bm,
        float* __restrict__ C, int M, int N, int K)
{
    __shared__ unsigned As[128 * SPITCH];
    __shared__ unsigned Bs[128 * SPITCH];

    int tid  = threadIdx.x;
    int lane = tid & 31;
    int warp = tid >> 5;
    int wm = (warp & 3) * 32;
    int wn = (warp >> 2) * 32;

    const float* Ab = A  + (size_t)blockIdx.y * 128 * K;
    const float* Bb = Bm + (size_t)blockIdx.x * 128 * K;

    int lr = tid >> 2;        // 0..127
    int lc = (tid & 3) * 8;   // 0,8,16,24

    float4 pa0 = *(const float4*)(Ab + (size_t)lr * K + lc);
    float4 pa1 = *(const float4*)(Ab + (size_t)lr * K + lc + 4);
    float4 pb0 = *(const float4*)(Bb + (size_t)lr * K + lc);
    float4 pb1 = *(const float4*)(Bb + (size_t)lr * K + lc + 4);

    float acc[8][4];
#pragma unroll
    for (int t = 0; t < 8; t++)
#pragma unroll
        for (int e = 0; e < 4; e++) acc[t][e] = 0.0f;

    int fr = lane >> 2;
    int fc = lane & 3;

    for (int k0 = 0; k0 < K; k0 += 32) {
        {
            uint4 u;
            u.x = f2tf32(pa0.x); u.y = f2tf32(pa0.y); u.z = f2tf32(pa0.z); u.w = f2tf32(pa0.w);
            *(uint4*)&As[lr * SPITCH + lc] = u;
            u.x = f2tf32(pa1.x); u.y = f2tf32(pa1.y); u.z = f2tf32(pa1.z); u.w = f2tf32(pa1.w);
            *(uint4*)&As[lr * SPITCH + lc + 4] = u;
            u.x = f2tf32(pb0.x); u.y = f2tf32(pb0.y); u.z = f2tf32(pb0.z); u.w = f2tf32(pb0.w);
            *(uint4*)&Bs[lr * SPITCH + lc] = u;
            u.x = f2tf32(pb1.x); u.y = f2tf32(pb1.y); u.z = f2tf32(pb1.z); u.w = f2tf32(pb1.w);
            *(uint4*)&Bs[lr * SPITCH + lc + 4] = u;
        }
        __syncthreads();

        if (k0 + 32 < K) {
            pa0 = *(const float4*)(Ab + (size_t)lr * K + k0 + 32 + lc);
            pa1 = *(const float4*)(Ab + (size_t)lr * K + k0 + 32 + lc + 4);
            pb0 = *(const float4*)(Bb + (size_t)lr * K + k0 + 32 + lc);
            pb1 = *(const float4*)(Bb + (size_t)lr * K + k0 + 32 + lc + 4);
        }

#pragma unroll
        for (int ks = 0; ks < 4; ks++) {
            int kb = ks * 8;
            unsigned af[2][4], bf[4][2];
#pragma unroll
            for (int mt = 0; mt < 2; mt++) {
                int m = wm + 16 * mt + fr;
                af[mt][0] = As[m * SPITCH + kb + fc];
                af[mt][1] = As[(m + 8) * SPITCH + kb + fc];
                af[mt][2] = As[m * SPITCH + kb + fc + 4];
                af[mt][3] = As[(m + 8) * SPITCH + kb + fc + 4];
            }
#pragma unroll
            for (int nt = 0; nt < 4; nt++) {
                int n = wn + 8 * nt + fr;
                bf[nt][0] = Bs[n * SPITCH + kb + fc];
                bf[nt][1] = Bs[n * SPITCH + kb + fc + 4];
            }
#pragma unroll
            for (int mt = 0; mt < 2; mt++)
#pragma unroll
                for (int nt = 0; nt < 4; nt++)
                    mma_tf32(acc[mt * 4 + nt], af[mt][0], af[mt][1], af[mt][2], af[mt][3],
                             bf[nt][0], bf[nt][1]);
        }
        __syncthreads();
    }

    int c2 = (lane & 3) * 2;
#pragma unroll
    for (int mt = 0; mt < 2; mt++) {
        size_t row0 = (size_t)blockIdx.y * 128 + wm + 16 * mt + fr;
#pragma unroll
        for (int nt = 0; nt < 4; nt++) {
            float* d = acc[mt * 4 + nt];
            size_t col = (size_t)blockIdx.x * 128 + wn + 8 * nt + c2;
            *(float2*)&C[row0 * N + col]       = make_float2(d[0], d[1]);
            *(float2*)&C[(row0 + 8) * N + col] = make_float2(d[2], d[3]);
        }
    }
}

// ---------------------------------------------------------------------------
// RMSNorm + RoPE + scatter into q/k/v buffers.
// ---------------------------------------------------------------------------
__global__ __launch_bounds__(512) void norm_rope_kernel(
        const float* __restrict__ fcos, const float* __restrict__ fsin,
        const int*   __restrict__ kvidx,
        const float* __restrict__ qw, const float* __restrict__ kw)
{
    int token = blockIdx.x;
    int b = token / NS;
    int s = token - b * NS;
    int warp = threadIdx.x >> 5;
    int lane = threadIdx.x & 31;

    const float* src = g_qkv + (size_t)token * ((NH + 2 * NKV) * ND) + warp * ND;

    float x1[4], x2[4];
#pragma unroll
    for (int i = 0; i < 4; i++) {
        x1[i] = src[lane + 32 * i];
        x2[i] = src[128 + lane + 32 * i];
    }

    if (warp >= 12) { // V: raw copy
        int kh = warp - 12;
        float* dst = g_v + ((size_t)(b * NKV + kh) * NS + kvidx[s]) * ND;
#pragma unroll
        for (int i = 0; i < 4; i++) {
            dst[lane + 32 * i]       = x1[i];
            dst[128 + lane + 32 * i] = x2[i];
        }
        return;
    }

    float ss = 0.0f;
#pragma unroll
    for (int i = 0; i < 4; i++) ss += x1[i] * x1[i] + x2[i] * x2[i];
#pragma unroll
    for (int m = 16; m; m >>= 1) ss += __shfl_xor_sync(0xffffffffu, ss, m);
    float inv = rsqrtf(ss * (1.0f / ND) + 1e-6f);

    const float* w   = (warp < 8) ? qw : kw;
    float scale      = (warp < 8) ? 0.0625f : 1.0f; // SCALING folded into q
    float* dst;
    if (warp < 8) dst = g_q + ((size_t)(b * NH + warp) * NS + s) * ND;
    else          dst = g_k + ((size_t)(b * NKV + (warp - 8)) * NS + kvidx[s]) * ND;

#pragma unroll
    for (int i = 0; i < 4; i++) {
        int d = lane + 32 * i;
        float c  = fcos[(size_t)s * 128 + d];
        float sn = fsin[(size_t)s * 128 + d];
        float y1 = x1[i] * inv * (1.0f + w[d]);
        float y2 = x2[i] * inv * (1.0f + w[d + 128]);
        dst[d]       = (y1 * c - y2 * sn) * scale;
        dst[d + 128] = (y2 * c + y1 * sn) * scale;
    }
}

// ---------------------------------------------------------------------------
// Sliding-window flash attention with tf32 mma.sync.
// BM=BN=64, D=256, 256 threads (8 warps).
// QK: warp (wr=warp&3, wc=warp>>2): m16 (rows 16wr..) x n32 (keys 32wc..)
// PV: warp owns d-slice [32*warp, 32*warp+32) over ALL 64 rows (V read once).
// Q/K/V all natural [row][d] layout, pitch 264 (8*fc+fr banks, conflict-free).
// ---------------------------------------------------------------------------
#define TP 264
#define PP 68

__global__ __launch_bounds__(256, 1) void attn_mma_kernel()
{
    extern __shared__ float smf[];
    unsigned* Qs = (unsigned*)smf;           // [64][TP]
    unsigned* Ks = Qs + 64 * TP;             // [64][TP]
    unsigned* Vs = Ks + 64 * TP;             // [64][TP]  (natural layout)
    float*    Ps = (float*)(Vs + 64 * TP);   // [64][PP]
    float*    ms = Ps + 64 * PP;             // [64]
    float*    ls = ms + 64;
    float*    cs = ls + 64;

    int qt = blockIdx.x, h = blockIdx.y, b = blockIdx.z;
    int q0 = qt * 64;
    int kh = h >> 1;

    const float* Qg = g_q + ((size_t)(b * NH + h) * NS + q0) * ND;
    const float* Kg = g_k + (size_t)(b * NKV + kh) * NS * ND;
    const float* Vg = g_v + (size_t)(b * NKV + kh) * NS * ND;

    int tid  = threadIdx.x;
    int lane = tid & 31;
    int warp = tid >> 5;
    int wr = warp & 3;
    int wc = warp >> 2;
    int fr = lane >> 2;
    int fc = lane & 3;

    // load Q tile as tf32
    for (int i = tid; i < 64 * 64; i += 256) {
        int r = i >> 6, c = (i & 63) << 2;
        float4 q4 = *(const float4*)(Qg + (size_t)r * ND + c);
        uint4 u;
        u.x = f2tf32(q4.x); u.y = f2tf32(q4.y);
        u.z = f2tf32(q4.z); u.w = f2tf32(q4.w);
        *(uint4*)&Qs[r * TP + c] = u;
    }
    if (tid < 64) { ms[tid] = -1e30f; ls[tid] = 0.0f; }

    float oacc[16][4]; // [mt*4+nt]: rows 16mt+fr/+8, cols 32*warp+8nt+2fc
#pragma unroll
    for (int t = 0; t < 16; t++)
#pragma unroll
        for (int e = 0; e < 4; e++) oacc[t][e] = 0.0f;

    int t0 = qt - 16; if (t0 < 0) t0 = 0;
    int r0 = 16 * wr + fr;

    for (int kt = t0; kt <= qt; kt++) {
        int k0 = kt * 64;
        __syncthreads();

        // K and V tiles, both natural layout
        for (int i = tid; i < 64 * 64; i += 256) {
            int r = i >> 6, c = (i & 63) << 2;
            float4 k4 = *(const float4*)(Kg + (size_t)(k0 + r) * ND + c);
            uint4 u;
            u.x = f2tf32(k4.x); u.y = f2tf32(k4.y);
            u.z = f2tf32(k4.z); u.w = f2tf32(k4.w);
            *(uint4*)&Ks[r * TP + c] = u;
            float4 v4 = *(const float4*)(Vg + (size_t)(k0 + r) * ND + c);
            u.x = f2tf32(v4.x); u.y = f2tf32(v4.y);
            u.z = f2tf32(v4.z); u.w = f2tf32(v4.w);
            *(uint4*)&Vs[r * TP + c] = u;
        }
        __syncthreads();

        // ---- scores: m16 x n32, k=256 ----
        float sacc[4][4];
#pragma unroll
        for (int t = 0; t < 4; t++)
#pragma unroll
            for (int e = 0; e < 4; e++) sacc[t][e] = 0.0f;

#pragma unroll 4
        for (int kb = 0; kb < 256; kb += 8) {
            unsigned a0 = Qs[r0 * TP + kb + fc];
            unsigned a1 = Qs[(r0 + 8) * TP + kb + fc];
            unsigned a2 = Qs[r0 * TP + kb + fc + 4];
            unsigned a3 = Qs[(r0 + 8) * TP + kb + fc + 4];
#pragma unroll
            for (int nt = 0; nt < 4; nt++) {
                int n = 32 * wc + 8 * nt + fr;
                unsigned b0 = Ks[n * TP + kb + fc];
                unsigned b1 = Ks[n * TP + kb + fc + 4];
                mma_tf32(sacc[nt], a0, a1, a2, a3, b0, b1);
            }
        }

        // softcap + mask -> Ps (raw scores, float)
        // 50*tanh(s/50) = 50 - 100/(exp(s/25)+1)   (|s| <= ~16, no overflow)
#pragma unroll
        for (int nt = 0; nt < 4; nt++) {
#pragma unroll
            for (int e = 0; e < 4; e++) {
                int r  = r0 + (e >> 1) * 8;
                int kj = k0 + 32 * wc + 8 * nt + 2 * fc + (e & 1);
                int qi = q0 + r;
                float ev = __expf(sacc[nt][e] * 0.04f);
                float v = 50.0f - 100.0f / (ev + 1.0f);
                bool ok = (kj <= qi) && (qi - kj < NWIN);
                sacc[nt][e] = ok ? v : -1e30f;
            }
            int col = 32 * wc + 8 * nt + 2 * fc;
            *(float2*)&Ps[r0 * PP + col]       = make_float2(sacc[nt][0], sacc[nt][1]);
            *(float2*)&Ps[(r0 + 8) * PP + col] = make_float2(sacc[nt][2], sacc[nt][3]);
        }
        __syncthreads();

        // ---- softmax: warp w owns rows 8w..8w+7; 4 lanes per row ----
        {
            int row = (warp << 3) + (lane >> 2);
            int cb  = lane & 3;
            float vbuf[16];
            float mx = -1e30f;
#pragma unroll
            for (int j = 0; j < 16; j++) {
                vbuf[j] = Ps[row * PP + cb + 4 * j];
                mx = fmaxf(mx, vbuf[j]);
            }
            mx = fmaxf(mx, __shfl_xor_sync(0xffffffffu, mx, 1));
            mx = fmaxf(mx, __shfl_xor_sync(0xffffffffu, mx, 2));
            float mold = ms[row];
            float mnew = fmaxf(mold, mx);
            float corr = __expf(mold - mnew);
            float rs = 0.0f;
#pragma unroll
            for (int j = 0; j < 16; j++) {
                float p = __expf(vbuf[j] - mnew);
                rs += p;
                Ps[row * PP + cb + 4 * j] = __uint_as_float(f2tf32(p));
            }
            rs += __shfl_xor_sync(0xffffffffu, rs, 1);
            rs += __shfl_xor_sync(0xffffffffu, rs, 2);
            if (cb == 0) {
                ms[row] = mnew;
                cs[row] = corr;
                ls[row] = ls[row] * corr + rs;
            }
        }
        __syncthreads();

        // ---- rescale O, then O += P @ V : warp does m64 x d32, k=64 ----
        {
            float cr0[4], cr1[4];
#pragma unroll
            for (int mt = 0; mt < 4; mt++) {
                cr0[mt] = cs[16 * mt + fr];
                cr1[mt] = cs[16 * mt + fr + 8];
            }
#pragma unroll
            for (int mt = 0; mt < 4; mt++)
#pragma unroll
                for (int nt = 0; nt < 4; nt++) {
                    float* d = oacc[mt * 4 + nt];
                    d[0] *= cr0[mt]; d[1] *= cr0[mt];
                    d[2] *= cr1[mt]; d[3] *= cr1[mt];
                }
#pragma unroll
            for (int kc = 0; kc < 64; kc += 8) {
                unsigned pa[4][4];
#pragma unroll
                for (int mt = 0; mt < 4; mt++) {
                    int r = 16 * mt + fr;
                    pa[mt][0] = __float_as_uint(Ps[r * PP + kc + fc]);
                    pa[mt][1] = __float_as_uint(Ps[(r + 8) * PP + kc + fc]);
                    pa[mt][2] = __float_as_uint(Ps[r * PP + kc + fc + 4]);
                    pa[mt][3] = __float_as_uint(Ps[(r + 8) * PP + kc + fc + 4]);
                }
                unsigned vb[4][2];
#pragma unroll
                for (int nt = 0; nt < 4; nt++) {
                    int dn = 32 * warp + 8 * nt + fr;
                    vb[nt][0] = Vs[(kc + fc) * TP + dn];
                    vb[nt][1] = Vs[(kc + fc + 4) * TP + dn];
                }
#pragma unroll
                for (int mt = 0; mt < 4; mt++)
#pragma unroll
                    for (int nt = 0; nt < 4; nt++)
                        mma_tf32(oacc[mt * 4 + nt], pa[mt][0], pa[mt][1], pa[mt][2], pa[mt][3],
                                 vb[nt][0], vb[nt][1]);
            }
        }
    }

    // epilogue
    {
        float* Og = g_att + ((size_t)b * NS + q0) * (NH * ND) + h * ND;
#pragma unroll
        for (int mt = 0; mt < 4; mt++) {
            int r = 16 * mt + fr;
            float il0 = 1.0f / ls[r];
            float il1 = 1.0f / ls[r + 8];
#pragma unroll
            for (int nt = 0; nt < 4; nt++) {
                float* d = oacc[mt * 4 + nt];
                int col = 32 * warp + 8 * nt + 2 * fc;
                *(float2*)&Og[(size_t)r * (NH * ND) + col] =
                    make_float2(d[0] * il0, d[1] * il0);
                *(float2*)&Og[(size_t)(r + 8) * (NH * ND) + col] =
                    make_float2(d[2] * il1, d[3] * il1);
            }
        }
    }
}

// ---------------------------------------------------------------------------
extern "C" void kernel_launch(void* const* d_in, const int* in_sizes, int n_in,
                              void* d_out, int out_size)
{
    const float* hidden = (const float*)d_in[0];
    const float* fcos   = (const float*)d_in[1];
    const float* fsin   = (const float*)d_in[2];
    const int*   kvidx  = (const int*)  d_in[3];
    const float* w_qkv  = (const float*)d_in[8];
    const float* w_o    = (const float*)d_in[9];
    const float* qnw    = (const float*)d_in[10];
    const float* knw    = (const float*)d_in[11];
    float* out = (float*)d_out;

    void* p;
    cudaGetSymbolAddress(&p, g_qkv); float* qkv_ptr = (float*)p;
    cudaGetSymbolAddress(&p, g_att); float* att_ptr = (float*)p;

    // 1) QKV projection (tf32 tensor cores)
    {
        dim3 grid((NH + 2 * NKV) * ND / 128, NB * NS / 128);
        tf32gemm_nt<<<grid, 512>>>(hidden, w_qkv, qkv_ptr,
                                   NB * NS, (NH + 2 * NKV) * ND, NE);
    }

    // 2) RMSNorm + RoPE + cache scatter
    norm_rope_kernel<<<NB * NS, 512>>>(fcos, fsin, kvidx, qnw, knw);

    // 3) sliding-window flash attention (tf32 tensor cores)
    {
        size_t smem = (size_t)(3 * 64 * TP + 64 * PP + 192) * 4;
        cudaFuncSetAttribute(attn_mma_kernel,
                             cudaFuncAttributeMaxDynamicSharedMemorySize,
                             (int)smem);
        dim3 grid(NS / 64, NH, NB);
        attn_mma_kernel<<<grid, 256, smem>>>();
    }

    // 4) output projection (tf32 tensor cores)
    {
        dim3 grid(NE / 128, NB * NS / 128);
        tf32gemm_nt<<<grid, 512>>>(att_ptr, w_o, out, NB * NS, NE, NH * ND);
    }
}